// round 13
// baseline (speedup 1.0000x reference)
#include <cuda_runtime.h>
#include <cuda_fp16.h>
#include <cstdint>
#include <math.h>

// Problem constants
#define BB      2
#define SS      2048
#define DM      4096
#define NH      32
#define NKV     8
#define HD      128
#define QKVD    6144          // (32 + 2*8) * 128
#define MROWS   4096          // B*S

// Scratch (allocation-free rule: __device__ globals)
__device__ __half g_qkv16[(size_t)MROWS * QKVD];   // fp16 qkv (RoPE in place)
__device__ __half g_attn [(size_t)MROWS * DM];     // fp16 attention output
__device__ __half g_rA   [(size_t)MROWS * DM];     // fp16 hidden_states
__device__ __half g_rWq  [(size_t)DM * QKVD];      // fp16 W_qkv, native [K][N]
__device__ __half g_rWo  [(size_t)DM * DM];        // fp16 W_out,  native [K][N]

__device__ __forceinline__ float ex2f(float x) {
    float r;
    asm("ex2.approx.f32 %0, %1;\n" : "=f"(r) : "f"(x));
    return r;
}
__device__ __forceinline__ void cp_async16(uint32_t smem, const void* gmem) {
    asm volatile("cp.async.cg.shared.global [%0], [%1], 16;\n" :: "r"(smem), "l"(gmem));
}
__device__ __forceinline__ void ldsm4(uint32_t* r, uint32_t addr) {
    asm volatile("ldmatrix.sync.aligned.m8n8.x4.shared.b16 {%0,%1,%2,%3}, [%4];"
                 : "=r"(r[0]), "=r"(r[1]), "=r"(r[2]), "=r"(r[3]) : "r"(addr));
}
__device__ __forceinline__ void ldsm4t(uint32_t* r, uint32_t addr) {
    asm volatile("ldmatrix.sync.aligned.m8n8.x4.trans.shared.b16 {%0,%1,%2,%3}, [%4];"
                 : "=r"(r[0]), "=r"(r[1]), "=r"(r[2]), "=r"(r[3]) : "r"(addr));
}
__device__ __forceinline__ void mma16816(float* d, const uint32_t* a,
                                         uint32_t b0, uint32_t b1) {
    asm volatile(
        "mma.sync.aligned.m16n8k16.row.col.f32.f16.f16.f32 "
        "{%0,%1,%2,%3}, {%4,%5,%6,%7}, {%8,%9}, {%0,%1,%2,%3};\n"
        : "+f"(d[0]), "+f"(d[1]), "+f"(d[2]), "+f"(d[3])
        : "r"(a[0]), "r"(a[1]), "r"(a[2]), "r"(a[3]), "r"(b0), "r"(b1));
}

// ---------------------------------------------------------------------------
// fp32 -> fp16 elementwise convert
// ---------------------------------------------------------------------------
__global__ void cvt_k(const float* __restrict__ in, __half* __restrict__ out, size_t n4)
{
    for (size_t i = (size_t)blockIdx.x * blockDim.x + threadIdx.x; i < n4;
         i += (size_t)gridDim.x * blockDim.x) {
        float4 v = ((const float4*)in)[i];
        __half2* o = (__half2*)out + 2 * i;
        o[0] = __floats2half2_rn(v.x, v.y);
        o[1] = __floats2half2_rn(v.z, v.w);
    }
}

// ---------------------------------------------------------------------------
// FP16 tensor-core GEMM: C[M,N] = A[M,K] @ B[K,N] (fp16 in; fp16/fp32 out).
// A row-major [M][K]; B native row-major [K][N] consumed via ldmatrix.trans.
// 128(M)x128(N) tile, k-chunks of 64 halves, 3-stage cp.async, 2 CTAs/SM.
// ---------------------------------------------------------------------------
#define HTBK 64                           // halves per k-tile
#define HPITCH 72                         // A pitch (144B rows, conflict-free)
#define BPITCH 136                        // B pitch (272B rows, conflict-free)
#define HNSTAGE 3
#define HATILE (128 * HPITCH)             // A tile halves (9216)
#define HBTILE (HTBK * BPITCH)            // B tile halves (8704)
#define HSTAGE (HATILE + HBTILE)          // 17920 halves = 35840 B
#define HG_SMEM_BYTES (HNSTAGE * HSTAGE * 2)   // 107520 B -> 2 CTAs/SM

template <typename OutT>
__global__ __launch_bounds__(256, 2) void hgemm_k(
    const __half* __restrict__ A, const __half* __restrict__ B,
    OutT* __restrict__ C, int M, int N, int K)
{
    extern __shared__ __align__(16) __half hsm[];
    const uint32_t tsu = (uint32_t)__cvta_generic_to_shared(hsm);

    const int tid  = threadIdx.x;
    const int lane = tid & 31;
    const int wid  = tid >> 5;
    const int wm   = wid >> 2;            // 0..1 -> 64 rows
    const int wn   = wid & 3;             // 0..3 -> 32 cols
    const int bm   = blockIdx.y * 128;
    const int bn   = blockIdx.x * 128;
    const int lq   = lane >> 2;
    const int lr   = lane & 3;

    const int q  = lane >> 3, rl = lane & 7;
    const int arow = (q & 1) * 8 + rl,  acol = (q >> 1) * 8;   // A / trans-B lane map

    float acc[4][4][4];
    #pragma unroll
    for (int i = 0; i < 4; i++)
        #pragma unroll
        for (int j = 0; j < 4; j++)
            #pragma unroll
            for (int c = 0; c < 4; c++) acc[i][j][c] = 0.f;

    const int KT = K / HTBK;

    auto issue = [&](int kt, int buf) {
        const uint32_t sAu = tsu + (uint32_t)(buf * HSTAGE) * 2;
        const uint32_t sBu = sAu + (uint32_t)HATILE * 2;
        const __half* Ag = A + (size_t)bm * K + kt * HTBK;
        const __half* Bg = B + (size_t)(kt * HTBK) * N + bn;
        #pragma unroll
        for (int qq = 0; qq < 4; qq++) {
            const int i = qq * 256 + tid;
            // A: 128 rows x 64 halves -> 1024 chunks of 16B
            const int ra = i >> 3, ca = (i & 7) * 8;
            cp_async16(sAu + (uint32_t)(ra * HPITCH + ca) * 2,
                       Ag + (size_t)ra * K + ca);
            // B: 64 rows x 128 halves -> 1024 chunks of 16B
            const int rb = i >> 4, cb = (i & 15) * 8;
            cp_async16(sBu + (uint32_t)(rb * BPITCH + cb) * 2,
                       Bg + (size_t)rb * N + cb);
        }
        asm volatile("cp.async.commit_group;\n");
    };

    issue(0, 0);
    issue(1, 1);

    for (int kt = 0; kt < KT; kt++) {
        asm volatile("cp.async.wait_group 1;\n");
        __syncthreads();

        const int nk = kt + 2;
        if (nk < KT) issue(nk, nk % HNSTAGE);
        else         asm volatile("cp.async.commit_group;\n");

        const uint32_t sAu = tsu + (uint32_t)((kt % HNSTAGE) * HSTAGE) * 2;
        const uint32_t sBu = sAu + (uint32_t)HATILE * 2;

        #pragma unroll
        for (int ks = 0; ks < 4; ks++) {
            const int k0 = ks * 16;
            uint32_t af[4][4], bf[2][4];
            #pragma unroll
            for (int mt = 0; mt < 4; mt++)
                ldsm4(af[mt], sAu + (uint32_t)((wm * 64 + mt * 16 + arow) * HPITCH
                                               + k0 + acol) * 2);
            #pragma unroll
            for (int p = 0; p < 2; p++)
                ldsm4t(bf[p], sBu + (uint32_t)((k0 + arow) * BPITCH
                                               + wn * 32 + p * 16 + acol) * 2);
            #pragma unroll
            for (int mt = 0; mt < 4; mt++)
                #pragma unroll
                for (int p = 0; p < 2; p++) {
                    mma16816(acc[mt][2 * p],     af[mt], bf[p][0], bf[p][1]);
                    mma16816(acc[mt][2 * p + 1], af[mt], bf[p][2], bf[p][3]);
                }
        }
        // no trailing syncthreads: with 3 stages the next iteration's top
        // barrier orders this iteration's readers before the stage is rewritten
    }

    #pragma unroll
    for (int mt = 0; mt < 4; mt++) {
        #pragma unroll
        for (int nt = 0; nt < 4; nt++) {
            const int row = bm + wm * 64 + mt * 16 + lq;
            const int col = bn + wn * 32 + nt * 8 + 2 * lr;
            if (sizeof(OutT) == 4) {
                float* c0 = (float*)C + (size_t)row * N + col;
                float* c1 = (float*)C + (size_t)(row + 8) * N + col;
                *(float2*)c0 = make_float2(acc[mt][nt][0], acc[mt][nt][1]);
                *(float2*)c1 = make_float2(acc[mt][nt][2], acc[mt][nt][3]);
            } else {
                __half* c0 = (__half*)C + (size_t)row * N + col;
                __half* c1 = (__half*)C + (size_t)(row + 8) * N + col;
                *(__half2*)c0 = __floats2half2_rn(acc[mt][nt][0], acc[mt][nt][1]);
                *(__half2*)c1 = __floats2half2_rn(acc[mt][nt][2], acc[mt][nt][3]);
            }
        }
    }
}

// ---------------------------------------------------------------------------
// RoPE in place on fp16 Q/K of g_qkv16 (V untouched — already fp16)
// ---------------------------------------------------------------------------
__global__ void rope16_k(const float* __restrict__ cost, const float* __restrict__ sint)
{
    const int row = blockIdx.x;            // 0..4095
    const int s   = row & (SS - 1);
    __half* qo = g_qkv16 + (size_t)row * QKVD;

    const int NROPE = (NH + NKV) * 64;     // 2560 rotation pairs
    for (int p = threadIdx.x; p < NROPE; p += blockDim.x) {
        const int h = p >> 6;
        const int d = p & 63;
        const int base = h * HD;
        const float c  = cost[s * HD + d];
        const float sn = sint[s * HD + d];
        const float x1 = __half2float(qo[base + d]);
        const float x2 = __half2float(qo[base + d + 64]);
        qo[base + d]      = __float2half_rn(x1 * c - x2 * sn);
        qo[base + d + 64] = __float2half_rn(x2 * c + x1 * sn);
    }
}

// ---------------------------------------------------------------------------
// Flash attention, fp16 mma.sync, cp.async pipelined K/V, LDSM everywhere.
// Heavy-tile-first launch order (qt reversed) to pack the wave tail.
// Q[128][136h] K 2x[64][136h] V[64][136h] P[128][72h] -> 105472 B, 2 CTAs/SM
// ---------------------------------------------------------------------------
#define QPH 136
#define KPH 136
#define VPH 136
#define SPH 72
#define FA_QO  0
#define FA_K0  (128 * QPH)
#define FA_K1  (FA_K0 + 64 * KPH)
#define FA_VO  (FA_K1 + 64 * KPH)
#define FA_PO  (FA_VO + 64 * VPH)
#define FA_SMEM_HALVES (FA_PO + 128 * SPH)
#define FA_SMEM_BYTES  (FA_SMEM_HALVES * 2)   // 105472 B

__global__ __launch_bounds__(256, 2) void fattn_k()
{
    extern __shared__ __align__(16) __half fsm[];
    __half* Qs = fsm + FA_QO;
    __half* Ps = fsm + FA_PO;
    const uint32_t bsu = (uint32_t)__cvta_generic_to_shared(fsm);
    const uint32_t qsu = bsu + FA_QO * 2;
    const uint32_t k0u = bsu + FA_K0 * 2;
    const uint32_t k1u = bsu + FA_K1 * 2;
    const uint32_t vsu = bsu + FA_VO * 2;
    const uint32_t psu = bsu + FA_PO * 2;

    const int qt  = (int)gridDim.x - 1 - (int)blockIdx.x;   // heavy tiles first
    const int qh  = blockIdx.y;
    const int b   = blockIdx.z;
    const int kh  = qh >> 2;
    const int tid = threadIdx.x;
    const int lane = tid & 31;
    const int w   = tid >> 5;
    const int lq  = lane >> 2;
    const int lr  = lane & 3;
    const int m0  = w * 16;

    const int q  = lane >> 3, rl = lane & 7;
    const int arow = (q & 1) * 8 + rl,  acol = (q >> 1) * 8;
    const int brow = (q >> 1) * 8 + rl, bcol = (q & 1) * 8;

    const __half* Qg = g_qkv16 + (size_t)(b * SS + qt * 128) * QKVD + qh * HD;
    const __half* Kg = g_qkv16 + (size_t)(b * SS) * QKVD + NH * HD + kh * HD;
    const __half* Vg = g_qkv16 + (size_t)(b * SS) * QKVD + (NH + NKV) * HD + kh * HD;

    const float scale2 = 0.08838834764831845f * 1.4426950408889634f;

    auto cpK = [&](int kt2, uint32_t dst) {
        #pragma unroll
        for (int qq = 0; qq < 4; qq++) {
            const int i = qq * 256 + tid;          // 1024 chunks of 16B
            const int r = i >> 4, c8 = (i & 15) * 8;
            cp_async16(dst + (uint32_t)(r * KPH + c8) * 2,
                       Kg + (size_t)(kt2 * 64 + r) * QKVD + c8);
        }
        asm volatile("cp.async.commit_group;\n");
    };
    auto cpV = [&](int kt2) {
        #pragma unroll
        for (int qq = 0; qq < 4; qq++) {
            const int i = qq * 256 + tid;
            const int r = i >> 4, c8 = (i & 15) * 8;
            cp_async16(vsu + (uint32_t)(r * VPH + c8) * 2,
                       Vg + (size_t)(kt2 * 64 + r) * QKVD + c8);
        }
        asm volatile("cp.async.commit_group;\n");
    };

    // Q load (plain vectorized) + prefetch K tile 0
    for (int i = tid; i < 128 * 16; i += 256) {
        const int r = i >> 4, c8 = (i & 15) * 8;
        *(uint4*)&Qs[r * QPH + c8] = *(const uint4*)(Qg + (size_t)r * QKVD + c8);
    }
    cpK(0, k0u);

    float oacc[16][4];
    #pragma unroll
    for (int i = 0; i < 16; i++)
        #pragma unroll
        for (int c = 0; c < 4; c++) oacc[i][c] = 0.f;
    float mrow0 = -1e30f, mrow1 = -1e30f;
    float lrow0 = 0.f,    lrow1 = 0.f;

    const int ktmax = 2 * qt + 2;
    for (int kt2 = 0; kt2 < ktmax; kt2++) {
        cpV(kt2);
        asm volatile("cp.async.wait_group 1;\n");    // K_cur complete
        __syncthreads();

        const uint32_t kcu = (kt2 & 1) ? k1u : k0u;

        // S = Q K^T
        float sacc[8][4];
        #pragma unroll
        for (int i = 0; i < 8; i++)
            #pragma unroll
            for (int c = 0; c < 4; c++) sacc[i][c] = 0.f;

        #pragma unroll
        for (int k = 0; k < 8; k++) {
            const int k0 = k * 16;
            uint32_t a[4], bf[4];
            ldsm4(a, qsu + (uint32_t)((m0 + arow) * QPH + k0 + acol) * 2);
            #pragma unroll
            for (int np = 0; np < 4; np++) {
                ldsm4(bf, kcu + (uint32_t)((np * 16 + brow) * KPH + k0 + bcol) * 2);
                mma16816(sacc[2 * np],     a, bf[0], bf[1]);
                mma16816(sacc[2 * np + 1], a, bf[2], bf[3]);
            }
        }

        const bool need_mask = (kt2 >= 2 * qt);
        const int r0 = qt * 128 + m0 + lq;
        const int r1 = r0 + 8;
        #pragma unroll
        for (int nt = 0; nt < 8; nt++) {
            const int colb = kt2 * 64 + nt * 8 + 2 * lr;
            #pragma unroll
            for (int c = 0; c < 4; c++) sacc[nt][c] *= scale2;
            if (need_mask) {
                if (colb     > r0) sacc[nt][0] = -1e30f;
                if (colb + 1 > r0) sacc[nt][1] = -1e30f;
                if (colb     > r1) sacc[nt][2] = -1e30f;
                if (colb + 1 > r1) sacc[nt][3] = -1e30f;
            }
        }

        // Online softmax (base-2 domain)
        float mx0 = -1e30f, mx1 = -1e30f;
        #pragma unroll
        for (int nt = 0; nt < 8; nt++) {
            mx0 = fmaxf(mx0, fmaxf(sacc[nt][0], sacc[nt][1]));
            mx1 = fmaxf(mx1, fmaxf(sacc[nt][2], sacc[nt][3]));
        }
        mx0 = fmaxf(mx0, __shfl_xor_sync(0xffffffffu, mx0, 1));
        mx0 = fmaxf(mx0, __shfl_xor_sync(0xffffffffu, mx0, 2));
        mx1 = fmaxf(mx1, __shfl_xor_sync(0xffffffffu, mx1, 1));
        mx1 = fmaxf(mx1, __shfl_xor_sync(0xffffffffu, mx1, 2));

        const float mn0 = fmaxf(mrow0, mx0);
        const float mn1 = fmaxf(mrow1, mx1);
        const float scl0 = ex2f(mrow0 - mn0);
        const float scl1 = ex2f(mrow1 - mn1);
        mrow0 = mn0; mrow1 = mn1;

        float rs0 = 0.f, rs1 = 0.f;
        #pragma unroll
        for (int nt = 0; nt < 8; nt++) {
            const float p0 = ex2f(sacc[nt][0] - mn0);
            const float p1 = ex2f(sacc[nt][1] - mn0);
            const float p2 = ex2f(sacc[nt][2] - mn1);
            const float p3 = ex2f(sacc[nt][3] - mn1);
            rs0 += p0 + p1;
            rs1 += p2 + p3;
            const int cb = nt * 8 + 2 * lr;
            *(__half2*)&Ps[(m0 + lq) * SPH + cb]     = __floats2half2_rn(p0, p1);
            *(__half2*)&Ps[(m0 + lq + 8) * SPH + cb] = __floats2half2_rn(p2, p3);
        }
        rs0 += __shfl_xor_sync(0xffffffffu, rs0, 1);
        rs0 += __shfl_xor_sync(0xffffffffu, rs0, 2);
        rs1 += __shfl_xor_sync(0xffffffffu, rs1, 1);
        rs1 += __shfl_xor_sync(0xffffffffu, rs1, 2);
        lrow0 = lrow0 * scl0 + rs0;
        lrow1 = lrow1 * scl1 + rs1;

        #pragma unroll
        for (int nt = 0; nt < 16; nt++) {
            oacc[nt][0] *= scl0; oacc[nt][1] *= scl0;
            oacc[nt][2] *= scl1; oacc[nt][3] *= scl1;
        }
        __syncwarp();   // this warp's P rows complete before LDSM reads

        if (kt2 + 1 < ktmax) cpK(kt2 + 1, ((kt2 + 1) & 1) ? k1u : k0u);
        else asm volatile("cp.async.commit_group;\n");

        asm volatile("cp.async.wait_group 1;\n");    // V_cur complete
        __syncthreads();

        // O += P V  (P via LDSM, V via LDSM.trans)
        #pragma unroll
        for (int k = 0; k < 4; k++) {
            const int k0 = k * 16;
            uint32_t a[4];
            ldsm4(a, psu + (uint32_t)((m0 + arow) * SPH + k0 + acol) * 2);
            #pragma unroll
            for (int np = 0; np < 8; np++) {
                uint32_t bf[4];
                ldsm4t(bf, vsu + (uint32_t)((k0 + arow) * VPH + np * 16 + acol) * 2);
                mma16816(oacc[2 * np],     a, bf[0], bf[1]);
                mma16816(oacc[2 * np + 1], a, bf[2], bf[3]);
            }
        }
        __syncthreads();   // protect Vs before next iteration's cpV
    }

    const float inv0 = 1.f / lrow0;
    const float inv1 = 1.f / lrow1;
    __half* Og = g_attn + (size_t)(b * SS + qt * 128 + m0 + lq) * DM + qh * HD;
    #pragma unroll
    for (int nt = 0; nt < 16; nt++) {
        const int cb = nt * 8 + 2 * lr;
        *(__half2*)(Og + cb) =
            __floats2half2_rn(oacc[nt][0] * inv0, oacc[nt][1] * inv0);
        *(__half2*)(Og + (size_t)8 * DM + cb) =
            __floats2half2_rn(oacc[nt][2] * inv1, oacc[nt][3] * inv1);
    }
}

// ---------------------------------------------------------------------------
// Launch
// ---------------------------------------------------------------------------
extern "C" void kernel_launch(void* const* d_in, const int* in_sizes, int n_in,
                              void* d_out, int out_size)
{
    const float* hs   = (const float*)d_in[0];
    const float* cosb = (const float*)d_in[1];
    const float* sinb = (const float*)d_in[2];
    const float* Wqkv = (const float*)d_in[3];
    const float* Wout = (const float*)d_in[4];
    float* out = (float*)d_out;

    __half *qkv16_ptr, *attn_ptr, *rA, *rWq, *rWo;
    cudaGetSymbolAddress((void**)&qkv16_ptr, g_qkv16);
    cudaGetSymbolAddress((void**)&attn_ptr,  g_attn);
    cudaGetSymbolAddress((void**)&rA,  g_rA);
    cudaGetSymbolAddress((void**)&rWq, g_rWq);
    cudaGetSymbolAddress((void**)&rWo, g_rWo);

    cudaFuncSetAttribute(hgemm_k<__half>, cudaFuncAttributeMaxDynamicSharedMemorySize,
                         HG_SMEM_BYTES);
    cudaFuncSetAttribute(hgemm_k<float>, cudaFuncAttributeMaxDynamicSharedMemorySize,
                         HG_SMEM_BYTES);
    cudaFuncSetAttribute(fattn_k, cudaFuncAttributeMaxDynamicSharedMemorySize,
                         FA_SMEM_BYTES);

    // 0) fp16 conversion (no transposes — B consumed K-major via ldmatrix.trans)
    cvt_k<<<592, 256>>>(hs,   rA,  (size_t)MROWS * DM / 4);
    cvt_k<<<592, 256>>>(Wqkv, rWq, (size_t)DM * QKVD / 4);
    cvt_k<<<592, 256>>>(Wout, rWo, (size_t)DM * DM / 4);

    // 1) QKV projection -> fp16 directly
    hgemm_k<__half><<<dim3(QKVD / 128, MROWS / 128), 256, HG_SMEM_BYTES>>>(
        rA, rWq, qkv16_ptr, MROWS, QKVD, DM);

    // 2) RoPE in place on fp16 Q/K
    rope16_k<<<MROWS, 256>>>(cosb, sinb);

    // 3) Causal GQA flash attention (fp16, heavy tiles first)
    fattn_k<<<dim3(SS / 128, NH, BB), 256, FA_SMEM_BYTES>>>();

    // 4) Output projection -> fp32
    hgemm_k<float><<<dim3(DM / 128, MROWS / 128), 256, HG_SMEM_BYTES>>>(
        attn_ptr, rWo, out, MROWS, DM, DM);
}

// round 14
// speedup vs baseline: 1.5537x; 1.5537x over previous
#include <cuda_runtime.h>
#include <cuda_fp16.h>
#include <cstdint>
#include <math.h>

// Problem constants
#define BB      2
#define SS      2048
#define DM      4096
#define NH      32
#define NKV     8
#define HD      128
#define QKVD    6144          // (32 + 2*8) * 128
#define MROWS   4096          // B*S

// Scratch (allocation-free rule: __device__ globals)
__device__ __half g_qkv16[(size_t)MROWS * QKVD];   // fp16 qkv (RoPE in place)
__device__ __half g_attn [(size_t)MROWS * DM];     // fp16 attention output
__device__ __half g_rA   [(size_t)MROWS * DM];     // fp16 hidden_states
__device__ __half g_rWq  [(size_t)DM * QKVD];      // fp16 W_qkv, TRANSPOSED [N][K]
__device__ __half g_rWo  [(size_t)DM * DM];        // fp16 W_out,  TRANSPOSED [N][K]

__device__ __forceinline__ float ex2f(float x) {
    float r;
    asm("ex2.approx.f32 %0, %1;\n" : "=f"(r) : "f"(x));
    return r;
}
__device__ __forceinline__ void cp_async16(uint32_t smem, const void* gmem) {
    asm volatile("cp.async.cg.shared.global [%0], [%1], 16;\n" :: "r"(smem), "l"(gmem));
}
__device__ __forceinline__ void ldsm4(uint32_t* r, uint32_t addr) {
    asm volatile("ldmatrix.sync.aligned.m8n8.x4.shared.b16 {%0,%1,%2,%3}, [%4];"
                 : "=r"(r[0]), "=r"(r[1]), "=r"(r[2]), "=r"(r[3]) : "r"(addr));
}
__device__ __forceinline__ void ldsm4t(uint32_t* r, uint32_t addr) {
    asm volatile("ldmatrix.sync.aligned.m8n8.x4.trans.shared.b16 {%0,%1,%2,%3}, [%4];"
                 : "=r"(r[0]), "=r"(r[1]), "=r"(r[2]), "=r"(r[3]) : "r"(addr));
}
__device__ __forceinline__ void mma16816(float* d, const uint32_t* a,
                                         uint32_t b0, uint32_t b1) {
    asm volatile(
        "mma.sync.aligned.m16n8k16.row.col.f32.f16.f16.f32 "
        "{%0,%1,%2,%3}, {%4,%5,%6,%7}, {%8,%9}, {%0,%1,%2,%3};\n"
        : "+f"(d[0]), "+f"(d[1]), "+f"(d[2]), "+f"(d[3])
        : "r"(a[0]), "r"(a[1]), "r"(a[2]), "r"(a[3]), "r"(b0), "r"(b1));
}

// ---------------------------------------------------------------------------
// fp32 -> fp16 elementwise convert
// ---------------------------------------------------------------------------
__global__ void cvt_k(const float* __restrict__ in, __half* __restrict__ out, size_t n4)
{
    for (size_t i = (size_t)blockIdx.x * blockDim.x + threadIdx.x; i < n4;
         i += (size_t)gridDim.x * blockDim.x) {
        float4 v = ((const float4*)in)[i];
        __half2* o = (__half2*)out + 2 * i;
        o[0] = __floats2half2_rn(v.x, v.y);
        o[1] = __floats2half2_rn(v.z, v.w);
    }
}

// ---------------------------------------------------------------------------
// Tiled transpose + fp16 convert: in[K][N] fp32 row-major -> out[N][K] fp16
// ---------------------------------------------------------------------------
__global__ void tcvt_k(const float* __restrict__ in, __half* __restrict__ out,
                       int K, int N)
{
    __shared__ float t[32][33];
    const int k0 = blockIdx.y * 32, n0 = blockIdx.x * 32;
    const int x = threadIdx.x, y = threadIdx.y;   // block (32, 8)
    #pragma unroll
    for (int i = 0; i < 32; i += 8)
        t[y + i][x] = in[(size_t)(k0 + y + i) * N + n0 + x];
    __syncthreads();
    #pragma unroll
    for (int i = 0; i < 32; i += 8)
        out[(size_t)(n0 + y + i) * K + k0 + x] = __float2half_rn(t[x][y + i]);
}

// ---------------------------------------------------------------------------
// FP16 tensor-core GEMM: C[M,N] = A[M,K] @ Bt[N,K]^T (fp16 in; fp16/fp32 out).
// 128x128 tile, k-chunks of 64 halves, 3-stage cp.async, 2 CTAs/SM, LDSM.
// (R12-proven hot loop; only the epilogue store type is templated.)
// ---------------------------------------------------------------------------
#define HTBK 64                           // halves per k-tile
#define HPITCH 72                         // halves (144B rows, LDSM conflict-free)
#define HNSTAGE 3
#define HTILE (128 * HPITCH)              // halves per operand tile
#define HSTAGE (2 * HTILE)
#define HG_SMEM_BYTES (HNSTAGE * HSTAGE * 2)   // 110592 B -> 2 CTAs/SM (216KB)

template <typename OutT>
__global__ __launch_bounds__(256, 2) void hgemm_k(
    const __half* __restrict__ A, const __half* __restrict__ Bt,
    OutT* __restrict__ C, int M, int N, int K)
{
    extern __shared__ __align__(16) __half hsm[];
    const uint32_t tsu = (uint32_t)__cvta_generic_to_shared(hsm);

    const int tid  = threadIdx.x;
    const int lane = tid & 31;
    const int wid  = tid >> 5;
    const int wm   = wid >> 2;            // 0..1 -> 64 rows
    const int wn   = wid & 3;             // 0..3 -> 32 cols
    const int bm   = blockIdx.y * 128;
    const int bn   = blockIdx.x * 128;
    const int lq   = lane >> 2;
    const int lr   = lane & 3;

    const int q  = lane >> 3, rl = lane & 7;
    const int arow = (q & 1) * 8 + rl,  acol = (q >> 1) * 8;   // A-frag lane map
    const int brow = (q >> 1) * 8 + rl, bcol = (q & 1) * 8;    // B-frag lane map

    float acc[4][4][4];
    #pragma unroll
    for (int i = 0; i < 4; i++)
        #pragma unroll
        for (int j = 0; j < 4; j++)
            #pragma unroll
            for (int c = 0; c < 4; c++) acc[i][j][c] = 0.f;

    const int KT = K / HTBK;

    auto issue = [&](int kt, int buf) {
        const uint32_t sAu = tsu + (uint32_t)(buf * HSTAGE) * 2;
        const uint32_t sBu = sAu + (uint32_t)HTILE * 2;
        const __half* Ag = A  + (size_t)bm * K + kt * HTBK;
        const __half* Bg = Bt + (size_t)bn * K + kt * HTBK;
        #pragma unroll
        for (int qq = 0; qq < 4; qq++) {
            const int i = qq * 256 + tid;          // 1024 chunks of 16B per tile
            const int row = i >> 3, c8 = (i & 7) * 8;
            cp_async16(sAu + (uint32_t)(row * HPITCH + c8) * 2,
                       Ag + (size_t)row * K + c8);
            cp_async16(sBu + (uint32_t)(row * HPITCH + c8) * 2,
                       Bg + (size_t)row * K + c8);
        }
        asm volatile("cp.async.commit_group;\n");
    };

    issue(0, 0);
    issue(1, 1);

    for (int kt = 0; kt < KT; kt++) {
        asm volatile("cp.async.wait_group 1;\n");
        __syncthreads();

        const int nk = kt + 2;
        if (nk < KT) issue(nk, nk % HNSTAGE);
        else         asm volatile("cp.async.commit_group;\n");

        const uint32_t sAu = tsu + (uint32_t)((kt % HNSTAGE) * HSTAGE) * 2;
        const uint32_t sBu = sAu + (uint32_t)HTILE * 2;

        #pragma unroll
        for (int ks = 0; ks < 4; ks++) {
            const int k0 = ks * 16;
            uint32_t af[4][4], bf[2][4];
            #pragma unroll
            for (int mt = 0; mt < 4; mt++)
                ldsm4(af[mt], sAu + (uint32_t)((wm * 64 + mt * 16 + arow) * HPITCH
                                               + k0 + acol) * 2);
            #pragma unroll
            for (int p = 0; p < 2; p++)
                ldsm4(bf[p], sBu + (uint32_t)((wn * 32 + p * 16 + brow) * HPITCH
                                              + k0 + bcol) * 2);
            #pragma unroll
            for (int mt = 0; mt < 4; mt++)
                #pragma unroll
                for (int p = 0; p < 2; p++) {
                    mma16816(acc[mt][2 * p],     af[mt], bf[p][0], bf[p][1]);
                    mma16816(acc[mt][2 * p + 1], af[mt], bf[p][2], bf[p][3]);
                }
        }
        // no trailing syncthreads: with 3 stages the next iteration's top
        // barrier orders this iteration's readers before the stage is rewritten
    }

    #pragma unroll
    for (int mt = 0; mt < 4; mt++) {
        #pragma unroll
        for (int nt = 0; nt < 4; nt++) {
            const int row = bm + wm * 64 + mt * 16 + lq;
            const int col = bn + wn * 32 + nt * 8 + 2 * lr;
            if (sizeof(OutT) == 4) {
                float* c0 = (float*)C + (size_t)row * N + col;
                float* c1 = (float*)C + (size_t)(row + 8) * N + col;
                *(float2*)c0 = make_float2(acc[mt][nt][0], acc[mt][nt][1]);
                *(float2*)c1 = make_float2(acc[mt][nt][2], acc[mt][nt][3]);
            } else {
                __half* c0 = (__half*)C + (size_t)row * N + col;
                __half* c1 = (__half*)C + (size_t)(row + 8) * N + col;
                *(__half2*)c0 = __floats2half2_rn(acc[mt][nt][0], acc[mt][nt][1]);
                *(__half2*)c1 = __floats2half2_rn(acc[mt][nt][2], acc[mt][nt][3]);
            }
        }
    }
}

// ---------------------------------------------------------------------------
// RoPE in place on fp16 Q/K of g_qkv16 (V untouched — already fp16)
// ---------------------------------------------------------------------------
__global__ void rope16_k(const float* __restrict__ cost, const float* __restrict__ sint)
{
    const int row = blockIdx.x;            // 0..4095
    const int s   = row & (SS - 1);
    __half* qo = g_qkv16 + (size_t)row * QKVD;

    const int NROPE = (NH + NKV) * 64;     // 2560 rotation pairs
    for (int p = threadIdx.x; p < NROPE; p += blockDim.x) {
        const int h = p >> 6;
        const int d = p & 63;
        const int base = h * HD;
        const float c  = cost[s * HD + d];
        const float sn = sint[s * HD + d];
        const float x1 = __half2float(qo[base + d]);
        const float x2 = __half2float(qo[base + d + 64]);
        qo[base + d]      = __float2half_rn(x1 * c - x2 * sn);
        qo[base + d + 64] = __float2half_rn(x2 * c + x1 * sn);
    }
}

// ---------------------------------------------------------------------------
// Flash attention, fp16 mma.sync, cp.async pipelined K/V, LDSM everywhere.
// Heavy-tile-first launch order (qt reversed) to pack the wave tail.
// Q[128][136h] K 2x[64][136h] V[64][136h] P[128][72h] -> 105472 B, 2 CTAs/SM
// ---------------------------------------------------------------------------
#define QPH 136
#define KPH 136
#define VPH 136
#define SPH 72
#define FA_QO  0
#define FA_K0  (128 * QPH)
#define FA_K1  (FA_K0 + 64 * KPH)
#define FA_VO  (FA_K1 + 64 * KPH)
#define FA_PO  (FA_VO + 64 * VPH)
#define FA_SMEM_HALVES (FA_PO + 128 * SPH)
#define FA_SMEM_BYTES  (FA_SMEM_HALVES * 2)   // 105472 B

__global__ __launch_bounds__(256, 2) void fattn_k()
{
    extern __shared__ __align__(16) __half fsm[];
    __half* Qs = fsm + FA_QO;
    __half* Ps = fsm + FA_PO;
    const uint32_t bsu = (uint32_t)__cvta_generic_to_shared(fsm);
    const uint32_t qsu = bsu + FA_QO * 2;
    const uint32_t k0u = bsu + FA_K0 * 2;
    const uint32_t k1u = bsu + FA_K1 * 2;
    const uint32_t vsu = bsu + FA_VO * 2;
    const uint32_t psu = bsu + FA_PO * 2;

    const int qt  = (int)gridDim.x - 1 - (int)blockIdx.x;   // heavy tiles first
    const int qh  = blockIdx.y;
    const int b   = blockIdx.z;
    const int kh  = qh >> 2;
    const int tid = threadIdx.x;
    const int lane = tid & 31;
    const int w   = tid >> 5;
    const int lq  = lane >> 2;
    const int lr  = lane & 3;
    const int m0  = w * 16;

    const int q  = lane >> 3, rl = lane & 7;
    const int arow = (q & 1) * 8 + rl,  acol = (q >> 1) * 8;
    const int brow = (q >> 1) * 8 + rl, bcol = (q & 1) * 8;

    const __half* Qg = g_qkv16 + (size_t)(b * SS + qt * 128) * QKVD + qh * HD;
    const __half* Kg = g_qkv16 + (size_t)(b * SS) * QKVD + NH * HD + kh * HD;
    const __half* Vg = g_qkv16 + (size_t)(b * SS) * QKVD + (NH + NKV) * HD + kh * HD;

    const float scale2 = 0.08838834764831845f * 1.4426950408889634f;

    auto cpK = [&](int kt2, uint32_t dst) {
        #pragma unroll
        for (int qq = 0; qq < 4; qq++) {
            const int i = qq * 256 + tid;          // 1024 chunks of 16B
            const int r = i >> 4, c8 = (i & 15) * 8;
            cp_async16(dst + (uint32_t)(r * KPH + c8) * 2,
                       Kg + (size_t)(kt2 * 64 + r) * QKVD + c8);
        }
        asm volatile("cp.async.commit_group;\n");
    };
    auto cpV = [&](int kt2) {
        #pragma unroll
        for (int qq = 0; qq < 4; qq++) {
            const int i = qq * 256 + tid;
            const int r = i >> 4, c8 = (i & 15) * 8;
            cp_async16(vsu + (uint32_t)(r * VPH + c8) * 2,
                       Vg + (size_t)(kt2 * 64 + r) * QKVD + c8);
        }
        asm volatile("cp.async.commit_group;\n");
    };

    // Q load (plain vectorized) + prefetch K tile 0
    for (int i = tid; i < 128 * 16; i += 256) {
        const int r = i >> 4, c8 = (i & 15) * 8;
        *(uint4*)&Qs[r * QPH + c8] = *(const uint4*)(Qg + (size_t)r * QKVD + c8);
    }
    cpK(0, k0u);

    float oacc[16][4];
    #pragma unroll
    for (int i = 0; i < 16; i++)
        #pragma unroll
        for (int c = 0; c < 4; c++) oacc[i][c] = 0.f;
    float mrow0 = -1e30f, mrow1 = -1e30f;
    float lrow0 = 0.f,    lrow1 = 0.f;

    const int ktmax = 2 * qt + 2;
    for (int kt2 = 0; kt2 < ktmax; kt2++) {
        cpV(kt2);
        asm volatile("cp.async.wait_group 1;\n");    // K_cur complete
        __syncthreads();

        const uint32_t kcu = (kt2 & 1) ? k1u : k0u;

        // S = Q K^T
        float sacc[8][4];
        #pragma unroll
        for (int i = 0; i < 8; i++)
            #pragma unroll
            for (int c = 0; c < 4; c++) sacc[i][c] = 0.f;

        #pragma unroll
        for (int k = 0; k < 8; k++) {
            const int k0 = k * 16;
            uint32_t a[4], bf[4];
            ldsm4(a, qsu + (uint32_t)((m0 + arow) * QPH + k0 + acol) * 2);
            #pragma unroll
            for (int np = 0; np < 4; np++) {
                ldsm4(bf, kcu + (uint32_t)((np * 16 + brow) * KPH + k0 + bcol) * 2);
                mma16816(sacc[2 * np],     a, bf[0], bf[1]);
                mma16816(sacc[2 * np + 1], a, bf[2], bf[3]);
            }
        }

        const bool need_mask = (kt2 >= 2 * qt);
        const int r0 = qt * 128 + m0 + lq;
        const int r1 = r0 + 8;
        #pragma unroll
        for (int nt = 0; nt < 8; nt++) {
            const int colb = kt2 * 64 + nt * 8 + 2 * lr;
            #pragma unroll
            for (int c = 0; c < 4; c++) sacc[nt][c] *= scale2;
            if (need_mask) {
                if (colb     > r0) sacc[nt][0] = -1e30f;
                if (colb + 1 > r0) sacc[nt][1] = -1e30f;
                if (colb     > r1) sacc[nt][2] = -1e30f;
                if (colb + 1 > r1) sacc[nt][3] = -1e30f;
            }
        }

        // Online softmax (base-2 domain)
        float mx0 = -1e30f, mx1 = -1e30f;
        #pragma unroll
        for (int nt = 0; nt < 8; nt++) {
            mx0 = fmaxf(mx0, fmaxf(sacc[nt][0], sacc[nt][1]));
            mx1 = fmaxf(mx1, fmaxf(sacc[nt][2], sacc[nt][3]));
        }
        mx0 = fmaxf(mx0, __shfl_xor_sync(0xffffffffu, mx0, 1));
        mx0 = fmaxf(mx0, __shfl_xor_sync(0xffffffffu, mx0, 2));
        mx1 = fmaxf(mx1, __shfl_xor_sync(0xffffffffu, mx1, 1));
        mx1 = fmaxf(mx1, __shfl_xor_sync(0xffffffffu, mx1, 2));

        const float mn0 = fmaxf(mrow0, mx0);
        const float mn1 = fmaxf(mrow1, mx1);
        const float scl0 = ex2f(mrow0 - mn0);
        const float scl1 = ex2f(mrow1 - mn1);
        mrow0 = mn0; mrow1 = mn1;

        float rs0 = 0.f, rs1 = 0.f;
        #pragma unroll
        for (int nt = 0; nt < 8; nt++) {
            const float p0 = ex2f(sacc[nt][0] - mn0);
            const float p1 = ex2f(sacc[nt][1] - mn0);
            const float p2 = ex2f(sacc[nt][2] - mn1);
            const float p3 = ex2f(sacc[nt][3] - mn1);
            rs0 += p0 + p1;
            rs1 += p2 + p3;
            const int cb = nt * 8 + 2 * lr;
            *(__half2*)&Ps[(m0 + lq) * SPH + cb]     = __floats2half2_rn(p0, p1);
            *(__half2*)&Ps[(m0 + lq + 8) * SPH + cb] = __floats2half2_rn(p2, p3);
        }
        rs0 += __shfl_xor_sync(0xffffffffu, rs0, 1);
        rs0 += __shfl_xor_sync(0xffffffffu, rs0, 2);
        rs1 += __shfl_xor_sync(0xffffffffu, rs1, 1);
        rs1 += __shfl_xor_sync(0xffffffffu, rs1, 2);
        lrow0 = lrow0 * scl0 + rs0;
        lrow1 = lrow1 * scl1 + rs1;

        #pragma unroll
        for (int nt = 0; nt < 16; nt++) {
            oacc[nt][0] *= scl0; oacc[nt][1] *= scl0;
            oacc[nt][2] *= scl1; oacc[nt][3] *= scl1;
        }
        __syncwarp();   // this warp's P rows complete before LDSM reads

        if (kt2 + 1 < ktmax) cpK(kt2 + 1, ((kt2 + 1) & 1) ? k1u : k0u);
        else asm volatile("cp.async.commit_group;\n");

        asm volatile("cp.async.wait_group 1;\n");    // V_cur complete
        __syncthreads();

        // O += P V  (P via LDSM, V via LDSM.trans)
        #pragma unroll
        for (int k = 0; k < 4; k++) {
            const int k0 = k * 16;
            uint32_t a[4];
            ldsm4(a, psu + (uint32_t)((m0 + arow) * SPH + k0 + acol) * 2);
            #pragma unroll
            for (int np = 0; np < 8; np++) {
                uint32_t bf[4];
                ldsm4t(bf, vsu + (uint32_t)((k0 + arow) * VPH + np * 16 + acol) * 2);
                mma16816(oacc[2 * np],     a, bf[0], bf[1]);
                mma16816(oacc[2 * np + 1], a, bf[2], bf[3]);
            }
        }
        __syncthreads();   // protect Vs before next iteration's cpV
    }

    const float inv0 = 1.f / lrow0;
    const float inv1 = 1.f / lrow1;
    __half* Og = g_attn + (size_t)(b * SS + qt * 128 + m0 + lq) * DM + qh * HD;
    #pragma unroll
    for (int nt = 0; nt < 16; nt++) {
        const int cb = nt * 8 + 2 * lr;
        *(__half2*)(Og + cb) =
            __floats2half2_rn(oacc[nt][0] * inv0, oacc[nt][1] * inv0);
        *(__half2*)(Og + (size_t)8 * DM + cb) =
            __floats2half2_rn(oacc[nt][2] * inv1, oacc[nt][3] * inv1);
    }
}

// ---------------------------------------------------------------------------
// Launch
// ---------------------------------------------------------------------------
extern "C" void kernel_launch(void* const* d_in, const int* in_sizes, int n_in,
                              void* d_out, int out_size)
{
    const float* hs   = (const float*)d_in[0];
    const float* cosb = (const float*)d_in[1];
    const float* sinb = (const float*)d_in[2];
    const float* Wqkv = (const float*)d_in[3];
    const float* Wout = (const float*)d_in[4];
    float* out = (float*)d_out;

    __half *qkv16_ptr, *attn_ptr, *rA, *rWq, *rWo;
    cudaGetSymbolAddress((void**)&qkv16_ptr, g_qkv16);
    cudaGetSymbolAddress((void**)&attn_ptr,  g_attn);
    cudaGetSymbolAddress((void**)&rA,  g_rA);
    cudaGetSymbolAddress((void**)&rWq, g_rWq);
    cudaGetSymbolAddress((void**)&rWo, g_rWo);

    cudaFuncSetAttribute(hgemm_k<__half>, cudaFuncAttributeMaxDynamicSharedMemorySize,
                         HG_SMEM_BYTES);
    cudaFuncSetAttribute(hgemm_k<float>, cudaFuncAttributeMaxDynamicSharedMemorySize,
                         HG_SMEM_BYTES);
    cudaFuncSetAttribute(fattn_k, cudaFuncAttributeMaxDynamicSharedMemorySize,
                         FA_SMEM_BYTES);

    // 0) fp16 conversion of activations; transpose+convert of weights
    cvt_k<<<592, 256>>>(hs, rA, (size_t)MROWS * DM / 4);
    tcvt_k<<<dim3(QKVD / 32, DM / 32), dim3(32, 8)>>>(Wqkv, rWq, DM, QKVD);
    tcvt_k<<<dim3(DM / 32, DM / 32),   dim3(32, 8)>>>(Wout, rWo, DM, DM);

    // 1) QKV projection -> fp16 directly
    hgemm_k<__half><<<dim3(QKVD / 128, MROWS / 128), 256, HG_SMEM_BYTES>>>(
        rA, rWq, qkv16_ptr, MROWS, QKVD, DM);

    // 2) RoPE in place on fp16 Q/K
    rope16_k<<<MROWS, 256>>>(cosb, sinb);

    // 3) Causal GQA flash attention (fp16, heavy tiles first)
    fattn_k<<<dim3(SS / 128, NH, BB), 256, FA_SMEM_BYTES>>>();

    // 4) Output projection -> fp32
    hgemm_k<float><<<dim3(DM / 128, MROWS / 128), 256, HG_SMEM_BYTES>>>(
        attn_ptr, rWo, out, MROWS, DM, DM);
}

// round 17
// speedup vs baseline: 1.5763x; 1.0146x over previous
#include <cuda_runtime.h>
#include <cuda_fp16.h>
#include <cstdint>
#include <math.h>

// Problem constants
#define BB      2
#define SS      2048
#define DM      4096
#define NH      32
#define NKV     8
#define HD      128
#define QKVD    6144          // (32 + 2*8) * 128
#define MROWS   4096          // B*S

// Scratch (allocation-free rule: __device__ globals)
__device__ __half g_qkv16[(size_t)MROWS * QKVD];   // fp16 qkv (RoPE in place)
__device__ __half g_attn [(size_t)MROWS * DM];     // fp16 attention output
__device__ __half g_rA   [(size_t)MROWS * DM];     // fp16 hidden_states
__device__ __half g_rWq  [(size_t)DM * QKVD];      // fp16 W_qkv, TRANSPOSED [N][K]
__device__ __half g_rWo  [(size_t)DM * DM];        // fp16 W_out,  TRANSPOSED [N][K]

__device__ __forceinline__ float ex2f(float x) {
    float r;
    asm("ex2.approx.f32 %0, %1;\n" : "=f"(r) : "f"(x));
    return r;
}
__device__ __forceinline__ void cp_async16(uint32_t smem, const void* gmem) {
    asm volatile("cp.async.cg.shared.global [%0], [%1], 16;\n" :: "r"(smem), "l"(gmem));
}
__device__ __forceinline__ void ldsm4(uint32_t* r, uint32_t addr) {
    asm volatile("ldmatrix.sync.aligned.m8n8.x4.shared.b16 {%0,%1,%2,%3}, [%4];"
                 : "=r"(r[0]), "=r"(r[1]), "=r"(r[2]), "=r"(r[3]) : "r"(addr));
}
__device__ __forceinline__ void ldsm4t(uint32_t* r, uint32_t addr) {
    asm volatile("ldmatrix.sync.aligned.m8n8.x4.trans.shared.b16 {%0,%1,%2,%3}, [%4];"
                 : "=r"(r[0]), "=r"(r[1]), "=r"(r[2]), "=r"(r[3]) : "r"(addr));
}
__device__ __forceinline__ void mma16816(float* d, const uint32_t* a,
                                         uint32_t b0, uint32_t b1) {
    asm volatile(
        "mma.sync.aligned.m16n8k16.row.col.f32.f16.f16.f32 "
        "{%0,%1,%2,%3}, {%4,%5,%6,%7}, {%8,%9}, {%0,%1,%2,%3};\n"
        : "+f"(d[0]), "+f"(d[1]), "+f"(d[2]), "+f"(d[3])
        : "r"(a[0]), "r"(a[1]), "r"(a[2]), "r"(a[3]), "r"(b0), "r"(b1));
}

// ---------------------------------------------------------------------------
// fp32 -> fp16 elementwise convert
// ---------------------------------------------------------------------------
__global__ void cvt_k(const float* __restrict__ in, __half* __restrict__ out, size_t n4)
{
    for (size_t i = (size_t)blockIdx.x * blockDim.x + threadIdx.x; i < n4;
         i += (size_t)gridDim.x * blockDim.x) {
        float4 v = ((const float4*)in)[i];
        __half2* o = (__half2*)out + 2 * i;
        o[0] = __floats2half2_rn(v.x, v.y);
        o[1] = __floats2half2_rn(v.z, v.w);
    }
}

// ---------------------------------------------------------------------------
// Vectorized tiled transpose + fp16 convert: in[K][N] fp32 -> out[N][K] fp16.
// 64x64 tile; gmem float4 loads + uint4 stores; smem scalar (pitch 65).
// ---------------------------------------------------------------------------
__global__ void tcvt2_k(const float* __restrict__ in, __half* __restrict__ out,
                        int K, int N)
{
    __shared__ float t[64][65];
    const int k0 = blockIdx.y * 64, n0 = blockIdx.x * 64;
    const int tid = threadIdx.x;

    #pragma unroll
    for (int q = 0; q < 4; q++) {              // 1024 float4 gmem loads
        const int i = q * 256 + tid;
        const int r = i >> 4, c4 = (i & 15) * 4;
        const float4 v = *(const float4*)(in + (size_t)(k0 + r) * N + n0 + c4);
        t[r][c4 + 0] = v.x;                    // scalar smem stores (pitch 65)
        t[r][c4 + 1] = v.y;
        t[r][c4 + 2] = v.z;
        t[r][c4 + 3] = v.w;
    }
    __syncthreads();

    #pragma unroll
    for (int q = 0; q < 2; q++) {              // 512 x 16B gmem stores
        const int i = q * 256 + tid;
        const int n = i >> 3, kg = (i & 7) * 8;
        uint4 pack;                             // 16B-aligned staging
        __half2* hp = (__half2*)&pack;
        #pragma unroll
        for (int j = 0; j < 4; j++)
            hp[j] = __floats2half2_rn(t[kg + 2 * j][n], t[kg + 2 * j + 1][n]);
        *(uint4*)(out + (size_t)(n0 + n) * K + k0 + kg) = pack;
    }
}

// ---------------------------------------------------------------------------
// FP16 tensor-core GEMM: C[M,N] = A[M,K] @ Bt[N,K]^T (fp16 in; fp16/fp32 out).
// 128x128 tile, k-chunks of 64 halves, 3-stage cp.async, 2 CTAs/SM, LDSM.
// ---------------------------------------------------------------------------
#define HTBK 64                           // halves per k-tile
#define HPITCH 72                         // halves (144B rows, LDSM conflict-free)
#define HNSTAGE 3
#define HTILE (128 * HPITCH)              // halves per operand tile
#define HSTAGE (2 * HTILE)
#define HG_SMEM_BYTES (HNSTAGE * HSTAGE * 2)   // 110592 B -> 2 CTAs/SM (216KB)

template <typename OutT>
__global__ __launch_bounds__(256, 2) void hgemm_k(
    const __half* __restrict__ A, const __half* __restrict__ Bt,
    OutT* __restrict__ C, int M, int N, int K)
{
    extern __shared__ __align__(16) __half hsm[];
    const uint32_t tsu = (uint32_t)__cvta_generic_to_shared(hsm);

    const int tid  = threadIdx.x;
    const int lane = tid & 31;
    const int wid  = tid >> 5;
    const int wm   = wid >> 2;            // 0..1 -> 64 rows
    const int wn   = wid & 3;             // 0..3 -> 32 cols
    const int bm   = blockIdx.y * 128;
    const int bn   = blockIdx.x * 128;
    const int lq   = lane >> 2;
    const int lr   = lane & 3;

    const int q  = lane >> 3, rl = lane & 7;
    const int arow = (q & 1) * 8 + rl,  acol = (q >> 1) * 8;   // A-frag lane map
    const int brow = (q >> 1) * 8 + rl, bcol = (q & 1) * 8;    // B-frag lane map

    float acc[4][4][4];
    #pragma unroll
    for (int i = 0; i < 4; i++)
        #pragma unroll
        for (int j = 0; j < 4; j++)
            #pragma unroll
            for (int c = 0; c < 4; c++) acc[i][j][c] = 0.f;

    const int KT = K / HTBK;

    auto issue = [&](int kt, int buf) {
        const uint32_t sAu = tsu + (uint32_t)(buf * HSTAGE) * 2;
        const uint32_t sBu = sAu + (uint32_t)HTILE * 2;
        const __half* Ag = A  + (size_t)bm * K + kt * HTBK;
        const __half* Bg = Bt + (size_t)bn * K + kt * HTBK;
        #pragma unroll
        for (int qq = 0; qq < 4; qq++) {
            const int i = qq * 256 + tid;          // 1024 chunks of 16B per tile
            const int row = i >> 3, c8 = (i & 7) * 8;
            cp_async16(sAu + (uint32_t)(row * HPITCH + c8) * 2,
                       Ag + (size_t)row * K + c8);
            cp_async16(sBu + (uint32_t)(row * HPITCH + c8) * 2,
                       Bg + (size_t)row * K + c8);
        }
        asm volatile("cp.async.commit_group;\n");
    };

    issue(0, 0);
    issue(1, 1);

    for (int kt = 0; kt < KT; kt++) {
        asm volatile("cp.async.wait_group 1;\n");
        __syncthreads();

        const int nk = kt + 2;
        if (nk < KT) issue(nk, nk % HNSTAGE);
        else         asm volatile("cp.async.commit_group;\n");

        const uint32_t sAu = tsu + (uint32_t)((kt % HNSTAGE) * HSTAGE) * 2;
        const uint32_t sBu = sAu + (uint32_t)HTILE * 2;

        #pragma unroll
        for (int ks = 0; ks < 4; ks++) {
            const int k0 = ks * 16;
            uint32_t af[4][4], bf[2][4];
            #pragma unroll
            for (int mt = 0; mt < 4; mt++)
                ldsm4(af[mt], sAu + (uint32_t)((wm * 64 + mt * 16 + arow) * HPITCH
                                               + k0 + acol) * 2);
            #pragma unroll
            for (int p = 0; p < 2; p++)
                ldsm4(bf[p], sBu + (uint32_t)((wn * 32 + p * 16 + brow) * HPITCH
                                              + k0 + bcol) * 2);
            #pragma unroll
            for (int mt = 0; mt < 4; mt++)
                #pragma unroll
                for (int p = 0; p < 2; p++) {
                    mma16816(acc[mt][2 * p],     af[mt], bf[p][0], bf[p][1]);
                    mma16816(acc[mt][2 * p + 1], af[mt], bf[p][2], bf[p][3]);
                }
        }
        // no trailing syncthreads: with 3 stages the next iteration's top
        // barrier orders this iteration's readers before the stage is rewritten
    }

    #pragma unroll
    for (int mt = 0; mt < 4; mt++) {
        #pragma unroll
        for (int nt = 0; nt < 4; nt++) {
            const int row = bm + wm * 64 + mt * 16 + lq;
            const int col = bn + wn * 32 + nt * 8 + 2 * lr;
            if (sizeof(OutT) == 4) {
                float* c0 = (float*)C + (size_t)row * N + col;
                float* c1 = (float*)C + (size_t)(row + 8) * N + col;
                *(float2*)c0 = make_float2(acc[mt][nt][0], acc[mt][nt][1]);
                *(float2*)c1 = make_float2(acc[mt][nt][2], acc[mt][nt][3]);
            } else {
                __half* c0 = (__half*)C + (size_t)row * N + col;
                __half* c1 = (__half*)C + (size_t)(row + 8) * N + col;
                *(__half2*)c0 = __floats2half2_rn(acc[mt][nt][0], acc[mt][nt][1]);
                *(__half2*)c1 = __floats2half2_rn(acc[mt][nt][2], acc[mt][nt][3]);
            }
        }
    }
}

// ---------------------------------------------------------------------------
// RoPE in place on fp16 Q/K of g_qkv16 (V untouched — already fp16)
// ---------------------------------------------------------------------------
__global__ void rope16_k(const float* __restrict__ cost, const float* __restrict__ sint)
{
    const int row = blockIdx.x;            // 0..4095
    const int s   = row & (SS - 1);
    __half* qo = g_qkv16 + (size_t)row * QKVD;

    const int NROPE = (NH + NKV) * 64;     // 2560 rotation pairs
    for (int p = threadIdx.x; p < NROPE; p += blockDim.x) {
        const int h = p >> 6;
        const int d = p & 63;
        const int base = h * HD;
        const float c  = cost[s * HD + d];
        const float sn = sint[s * HD + d];
        const float x1 = __half2float(qo[base + d]);
        const float x2 = __half2float(qo[base + d + 64]);
        qo[base + d]      = __float2half_rn(x1 * c - x2 * sn);
        qo[base + d + 64] = __float2half_rn(x2 * c + x1 * sn);
    }
}

// ---------------------------------------------------------------------------
// Flash attention, fp16 mma.sync, cp.async pipelined K/V, LDSM everywhere.
// Q pre-scaled by scale*log2e at load; h2exp2 softmax (fp16x2 MUFU).
// Heavy-tile-first launch order. 105472 B smem, 2 CTAs/SM.
// ---------------------------------------------------------------------------
#define QPH 136
#define KPH 136
#define VPH 136
#define SPH 72
#define FA_QO  0
#define FA_K0  (128 * QPH)
#define FA_K1  (FA_K0 + 64 * KPH)
#define FA_VO  (FA_K1 + 64 * KPH)
#define FA_PO  (FA_VO + 64 * VPH)
#define FA_SMEM_HALVES (FA_PO + 128 * SPH)
#define FA_SMEM_BYTES  (FA_SMEM_HALVES * 2)   // 105472 B

__global__ __launch_bounds__(256, 2) void fattn_k()
{
    extern __shared__ __align__(16) __half fsm[];
    __half* Qs = fsm + FA_QO;
    __half* Ps = fsm + FA_PO;
    const uint32_t bsu = (uint32_t)__cvta_generic_to_shared(fsm);
    const uint32_t qsu = bsu + FA_QO * 2;
    const uint32_t k0u = bsu + FA_K0 * 2;
    const uint32_t k1u = bsu + FA_K1 * 2;
    const uint32_t vsu = bsu + FA_VO * 2;
    const uint32_t psu = bsu + FA_PO * 2;

    const int qt  = (int)gridDim.x - 1 - (int)blockIdx.x;   // heavy tiles first
    const int qh  = blockIdx.y;
    const int b   = blockIdx.z;
    const int kh  = qh >> 2;
    const int tid = threadIdx.x;
    const int lane = tid & 31;
    const int w   = tid >> 5;
    const int lq  = lane >> 2;
    const int lr  = lane & 3;
    const int m0  = w * 16;

    const int q  = lane >> 3, rl = lane & 7;
    const int arow = (q & 1) * 8 + rl,  acol = (q >> 1) * 8;
    const int brow = (q >> 1) * 8 + rl, bcol = (q & 1) * 8;

    const __half* Qg = g_qkv16 + (size_t)(b * SS + qt * 128) * QKVD + qh * HD;
    const __half* Kg = g_qkv16 + (size_t)(b * SS) * QKVD + NH * HD + kh * HD;
    const __half* Vg = g_qkv16 + (size_t)(b * SS) * QKVD + (NH + NKV) * HD + kh * HD;

    // scale * log2(e), folded into Q at load time
    const __half2 s2h = __float2half2_rn(0.08838834764831845f * 1.4426950408889634f);

    auto cpK = [&](int kt2, uint32_t dst) {
        #pragma unroll
        for (int qq = 0; qq < 4; qq++) {
            const int i = qq * 256 + tid;          // 1024 chunks of 16B
            const int r = i >> 4, c8 = (i & 15) * 8;
            cp_async16(dst + (uint32_t)(r * KPH + c8) * 2,
                       Kg + (size_t)(kt2 * 64 + r) * QKVD + c8);
        }
        asm volatile("cp.async.commit_group;\n");
    };
    auto cpV = [&](int kt2) {
        #pragma unroll
        for (int qq = 0; qq < 4; qq++) {
            const int i = qq * 256 + tid;
            const int r = i >> 4, c8 = (i & 15) * 8;
            cp_async16(vsu + (uint32_t)(r * VPH + c8) * 2,
                       Vg + (size_t)(kt2 * 64 + r) * QKVD + c8);
        }
        asm volatile("cp.async.commit_group;\n");
    };

    // Q load, pre-scaled, + prefetch K tile 0
    for (int i = tid; i < 128 * 16; i += 256) {
        const int r = i >> 4, c8 = (i & 15) * 8;
        uint4 v = *(const uint4*)(Qg + (size_t)r * QKVD + c8);
        __half2* hv = (__half2*)&v;
        #pragma unroll
        for (int j = 0; j < 4; j++) hv[j] = __hmul2(hv[j], s2h);
        *(uint4*)&Qs[r * QPH + c8] = v;
    }
    cpK(0, k0u);

    float oacc[16][4];
    #pragma unroll
    for (int i = 0; i < 16; i++)
        #pragma unroll
        for (int c = 0; c < 4; c++) oacc[i][c] = 0.f;
    float mrow0 = -1e30f, mrow1 = -1e30f;
    float lrow0 = 0.f,    lrow1 = 0.f;

    const int ktmax = 2 * qt + 2;
    for (int kt2 = 0; kt2 < ktmax; kt2++) {
        cpV(kt2);
        asm volatile("cp.async.wait_group 1;\n");    // K_cur complete
        __syncthreads();

        const uint32_t kcu = (kt2 & 1) ? k1u : k0u;

        // S = Q K^T  (already scaled via Q)
        float sacc[8][4];
        #pragma unroll
        for (int i = 0; i < 8; i++)
            #pragma unroll
            for (int c = 0; c < 4; c++) sacc[i][c] = 0.f;

        #pragma unroll
        for (int k = 0; k < 8; k++) {
            const int k0 = k * 16;
            uint32_t a[4], bf[4];
            ldsm4(a, qsu + (uint32_t)((m0 + arow) * QPH + k0 + acol) * 2);
            #pragma unroll
            for (int np = 0; np < 4; np++) {
                ldsm4(bf, kcu + (uint32_t)((np * 16 + brow) * KPH + k0 + bcol) * 2);
                mma16816(sacc[2 * np],     a, bf[0], bf[1]);
                mma16816(sacc[2 * np + 1], a, bf[2], bf[3]);
            }
        }

        // Causal mask
        if (kt2 >= 2 * qt) {
            const int r0 = qt * 128 + m0 + lq;
            const int r1 = r0 + 8;
            #pragma unroll
            for (int nt = 0; nt < 8; nt++) {
                const int colb = kt2 * 64 + nt * 8 + 2 * lr;
                if (colb     > r0) sacc[nt][0] = -1e30f;
                if (colb + 1 > r0) sacc[nt][1] = -1e30f;
                if (colb     > r1) sacc[nt][2] = -1e30f;
                if (colb + 1 > r1) sacc[nt][3] = -1e30f;
            }
        }

        // Online softmax (base-2 domain; fp16x2 exp)
        float mx0 = -1e30f, mx1 = -1e30f;
        #pragma unroll
        for (int nt = 0; nt < 8; nt++) {
            mx0 = fmaxf(mx0, fmaxf(sacc[nt][0], sacc[nt][1]));
            mx1 = fmaxf(mx1, fmaxf(sacc[nt][2], sacc[nt][3]));
        }
        mx0 = fmaxf(mx0, __shfl_xor_sync(0xffffffffu, mx0, 1));
        mx0 = fmaxf(mx0, __shfl_xor_sync(0xffffffffu, mx0, 2));
        mx1 = fmaxf(mx1, __shfl_xor_sync(0xffffffffu, mx1, 1));
        mx1 = fmaxf(mx1, __shfl_xor_sync(0xffffffffu, mx1, 2));

        const float mn0 = fmaxf(mrow0, mx0);
        const float mn1 = fmaxf(mrow1, mx1);
        const float scl0 = ex2f(mrow0 - mn0);
        const float scl1 = ex2f(mrow1 - mn1);
        mrow0 = mn0; mrow1 = mn1;

        float rs0 = 0.f, rs1 = 0.f;
        #pragma unroll
        for (int nt = 0; nt < 8; nt++) {
            const __half2 e0 = h2exp2(__floats2half2_rn(sacc[nt][0] - mn0,
                                                        sacc[nt][1] - mn0));
            const __half2 e1 = h2exp2(__floats2half2_rn(sacc[nt][2] - mn1,
                                                        sacc[nt][3] - mn1));
            const float2 f0 = __half22float2(e0);
            const float2 f1 = __half22float2(e1);
            rs0 += f0.x + f0.y;
            rs1 += f1.x + f1.y;
            const int cb = nt * 8 + 2 * lr;
            *(__half2*)&Ps[(m0 + lq) * SPH + cb]     = e0;
            *(__half2*)&Ps[(m0 + lq + 8) * SPH + cb] = e1;
        }
        rs0 += __shfl_xor_sync(0xffffffffu, rs0, 1);
        rs0 += __shfl_xor_sync(0xffffffffu, rs0, 2);
        rs1 += __shfl_xor_sync(0xffffffffu, rs1, 1);
        rs1 += __shfl_xor_sync(0xffffffffu, rs1, 2);
        lrow0 = lrow0 * scl0 + rs0;
        lrow1 = lrow1 * scl1 + rs1;

        #pragma unroll
        for (int nt = 0; nt < 16; nt++) {
            oacc[nt][0] *= scl0; oacc[nt][1] *= scl0;
            oacc[nt][2] *= scl1; oacc[nt][3] *= scl1;
        }
        __syncwarp();   // this warp's P rows complete before LDSM reads

        if (kt2 + 1 < ktmax) cpK(kt2 + 1, ((kt2 + 1) & 1) ? k1u : k0u);
        else asm volatile("cp.async.commit_group;\n");

        asm volatile("cp.async.wait_group 1;\n");    // V_cur complete
        __syncthreads();

        // O += P V  (P via LDSM, V via LDSM.trans)
        #pragma unroll
        for (int k = 0; k < 4; k++) {
            const int k0 = k * 16;
            uint32_t a[4];
            ldsm4(a, psu + (uint32_t)((m0 + arow) * SPH + k0 + acol) * 2);
            #pragma unroll
            for (int np = 0; np < 8; np++) {
                uint32_t bf[4];
                ldsm4t(bf, vsu + (uint32_t)((k0 + arow) * VPH + np * 16 + acol) * 2);
                mma16816(oacc[2 * np],     a, bf[0], bf[1]);
                mma16816(oacc[2 * np + 1], a, bf[2], bf[3]);
            }
        }
        __syncthreads();   // protect Vs before next iteration's cpV
    }

    const float inv0 = 1.f / lrow0;
    const float inv1 = 1.f / lrow1;
    __half* Og = g_attn + (size_t)(b * SS + qt * 128 + m0 + lq) * DM + qh * HD;
    #pragma unroll
    for (int nt = 0; nt < 16; nt++) {
        const int cb = nt * 8 + 2 * lr;
        *(__half2*)(Og + cb) =
            __floats2half2_rn(oacc[nt][0] * inv0, oacc[nt][1] * inv0);
        *(__half2*)(Og + (size_t)8 * DM + cb) =
            __floats2half2_rn(oacc[nt][2] * inv1, oacc[nt][3] * inv1);
    }
}

// ---------------------------------------------------------------------------
// Launch
// ---------------------------------------------------------------------------
extern "C" void kernel_launch(void* const* d_in, const int* in_sizes, int n_in,
                              void* d_out, int out_size)
{
    const float* hs   = (const float*)d_in[0];
    const float* cosb = (const float*)d_in[1];
    const float* sinb = (const float*)d_in[2];
    const float* Wqkv = (const float*)d_in[3];
    const float* Wout = (const float*)d_in[4];
    float* out = (float*)d_out;

    __half *qkv16_ptr, *attn_ptr, *rA, *rWq, *rWo;
    cudaGetSymbolAddress((void**)&qkv16_ptr, g_qkv16);
    cudaGetSymbolAddress((void**)&attn_ptr,  g_attn);
    cudaGetSymbolAddress((void**)&rA,  g_rA);
    cudaGetSymbolAddress((void**)&rWq, g_rWq);
    cudaGetSymbolAddress((void**)&rWo, g_rWo);

    cudaFuncSetAttribute(hgemm_k<__half>, cudaFuncAttributeMaxDynamicSharedMemorySize,
                         HG_SMEM_BYTES);
    cudaFuncSetAttribute(hgemm_k<float>, cudaFuncAttributeMaxDynamicSharedMemorySize,
                         HG_SMEM_BYTES);
    cudaFuncSetAttribute(fattn_k, cudaFuncAttributeMaxDynamicSharedMemorySize,
                         FA_SMEM_BYTES);

    // 0) fp16 conversion of activations; vectorized transpose+convert of weights
    cvt_k<<<592, 256>>>(hs, rA, (size_t)MROWS * DM / 4);
    tcvt2_k<<<dim3(QKVD / 64, DM / 64), 256>>>(Wqkv, rWq, DM, QKVD);
    tcvt2_k<<<dim3(DM / 64, DM / 64),   256>>>(Wout, rWo, DM, DM);

    // 1) QKV projection -> fp16 directly
    hgemm_k<__half><<<dim3(QKVD / 128, MROWS / 128), 256, HG_SMEM_BYTES>>>(
        rA, rWq, qkv16_ptr, MROWS, QKVD, DM);

    // 2) RoPE in place on fp16 Q/K
    rope16_k<<<MROWS, 256>>>(cosb, sinb);

    // 3) Causal GQA flash attention (fp16, heavy tiles first)
    fattn_k<<<dim3(SS / 128, NH, BB), 256, FA_SMEM_BYTES>>>();

    // 4) Output projection -> fp32
    hgemm_k<float><<<dim3(DM / 128, MROWS / 128), 256, HG_SMEM_BYTES>>>(
        attn_ptr, rWo, out, MROWS, DM, DM);
}